// round 16
// baseline (speedup 1.0000x reference)
#include <cuda_runtime.h>
#include <cuda_bf16.h>
#include <cstdint>

// ---------------------------------------------------------------------------
// UpsampleUpdatingModel2 — split-bf16 implicit-GEMM convs on mma.sync (HMMA)
// R15: R11 mainloop (best: 3920us) + COMPILE-TIME templated epilogues:
//      fused bf16 hi/lo xt emit (prep_xt deleted) without register-union cost.
// ---------------------------------------------------------------------------

#define N_IMG 24
#define CH    256
#define HH    56
#define WW    56
#define HWP   3136
#define PW    58
#define PHWP  3248
#define XT_ELEMS ((size_t)N_IMG * PHWP * CH)

__device__ __align__(128) float g_pm  [N_IMG * 2 * HWP];
__device__ __align__(128) float g_bufC[N_IMG * CH * HWP];            // emb (fp32)
__device__ __align__(128) __nv_bfloat16 g_E0h[XT_ELEMS], g_E0l[XT_ELEMS];
__device__ __align__(128) __nv_bfloat16 g_E1h[XT_ELEMS], g_E1l[XT_ELEMS];
__device__ __align__(128) __nv_bfloat16 g_P0h[XT_ELEMS], g_P0l[XT_ELEMS];
__device__ __align__(128) __nv_bfloat16 g_P1h[XT_ELEMS], g_P1l[XT_ELEMS];
__device__ __align__(128) __nv_bfloat16 g_wA_hi[9 * CH * CH];        // [tap][oc][ic]
__device__ __align__(128) __nv_bfloat16 g_wA_lo[9 * CH * CH];
__device__ __align__(128) __nv_bfloat16 g_wd_hi[CH * CH];
__device__ __align__(128) __nv_bfloat16 g_wd_lo[CH * CH];

static inline int cdiv(int a, int b) { return (a + b - 1) / b; }

// ------------------------------ PTX helpers --------------------------------
__device__ __forceinline__ uint32_t smem_u32(const void* p) {
    uint32_t a;
    asm("{ .reg .u64 t; cvta.to.shared.u64 t, %1; cvt.u32.u64 %0, t; }" : "=r"(a) : "l"(p));
    return a;
}
__device__ __forceinline__ void ldsm_x4(uint32_t* r, uint32_t addr) {
    asm volatile("ldmatrix.sync.aligned.m8n8.x4.shared.b16 {%0,%1,%2,%3}, [%4];"
                 : "=r"(r[0]), "=r"(r[1]), "=r"(r[2]), "=r"(r[3]) : "r"(addr));
}
__device__ __forceinline__ void ldsm_x2(uint32_t* r, uint32_t addr) {
    asm volatile("ldmatrix.sync.aligned.m8n8.x2.shared.b16 {%0,%1}, [%2];"
                 : "=r"(r[0]), "=r"(r[1]) : "r"(addr));
}
__device__ __forceinline__ void mma16816(float* d, const uint32_t* a, const uint32_t* b) {
    asm volatile(
        "mma.sync.aligned.m16n8k16.row.col.f32.bf16.bf16.f32 "
        "{%0,%1,%2,%3}, {%4,%5,%6,%7}, {%8,%9}, {%0,%1,%2,%3};"
        : "+f"(d[0]), "+f"(d[1]), "+f"(d[2]), "+f"(d[3])
        : "r"(a[0]), "r"(a[1]), "r"(a[2]), "r"(a[3]), "r"(b[0]), "r"(b[1]));
}
__device__ __forceinline__ void cpa16(uint32_t dst, const void* src, bool valid) {
    asm volatile("cp.async.cg.shared.global [%0], [%1], 16, %2;"
                 :: "r"(dst), "l"(src), "r"(valid ? 16u : 0u));
}
#define CPA_COMMIT() asm volatile("cp.async.commit_group;")
template <int N>
__device__ __forceinline__ void cpa_wait() {
    asm volatile("cp.async.wait_group %0;" :: "n"(N));
}

// SMEM: K-major tiles, 64 ic/stage, row stride 144B. A double-buf, B single.
#define RS     144
#define A_BUF  (2 * 128 * RS)
#define SM_A0  0
#define SM_A1  (SM_A0 + A_BUF)
#define SM_B   (SM_A1 + A_BUF)
#define SM_TOT (SM_B + 2 * 116 * RS)        // 107136 -> occ 2

// ---------------------------------------------------------------------------
__global__ void downsample_k(const float* __restrict__ src, float* __restrict__ dst) {
    int idx = blockIdx.x * 256 + threadIdx.x;
    if (idx >= 48 * HWP) return;
    int nc = idx / HWP, p = idx - nc * HWP;
    int i = p / WW, j = p - i * WW;
    const float* s = src + (size_t)nc * 112 * 112;
    int base = (2 * i) * 112 + 2 * j;
    dst[idx] = (s[base] + s[base + 1] + s[base + 112] + s[base + 113]) * 0.0625f;
}

// ---------------------------------------------------------------------------
__global__ void init_pads_k() {
    int idx = blockIdx.x * 256 + threadIdx.x;
    if (idx >= N_IMG * HH * 2 * 32) return;
    int g    = idx & 31;
    int side = (idx >> 5) & 1;
    int r    = (idx >> 6) % HH;
    int img  = idx / (HH * 2 * 32);
    size_t dst = ((size_t)img * PHWP + r * PW + (side ? 57 : 0)) * CH + g * 8;
    uint4 z = {0, 0, 0, 0};
    *(uint4*)(g_E0h + dst) = z;  *(uint4*)(g_E0l + dst) = z;
    *(uint4*)(g_E1h + dst) = z;  *(uint4*)(g_E1l + dst) = z;
    *(uint4*)(g_P0h + dst) = z;  *(uint4*)(g_P0l + dst) = z;
    *(uint4*)(g_P1h + dst) = z;  *(uint4*)(g_P1l + dst) = z;
}

// ---------------------------------------------------------------------------
// merged input producers: y==0 conv_first(pm)->E0 ; y==1 deform(feat,pm)->P0
// ---------------------------------------------------------------------------
__global__ void prep_in_k(const float* __restrict__ pm, const float* __restrict__ feat,
                          const float* __restrict__ ew1, const float* __restrict__ eb1) {
    int idx = blockIdx.x * 256 + threadIdx.x;
    if (idx >= N_IMG * HWP * 32) return;
    int cg  = idx & 31;
    int px  = (idx >> 5) % HWP;
    int img = idx / (32 * HWP);
    int i = px / WW, j = px - i * WW;

    float v8[8];
    if (blockIdx.y == 0) {
        #pragma unroll
        for (int k = 0; k < 8; k++) v8[k] = eb1[cg * 8 + k];
        #pragma unroll
        for (int c = 0; c < 2; c++) {
            const float* pc = pm + (size_t)(img * 2 + c) * HWP;
            #pragma unroll
            for (int dy = 0; dy < 3; dy++) {
                int y = i + dy - 1;
                if ((unsigned)y >= (unsigned)HH) continue;
                #pragma unroll
                for (int dx = 0; dx < 3; dx++) {
                    int x = j + dx - 1;
                    if ((unsigned)x >= (unsigned)WW) continue;
                    float v = pc[y * WW + x];
                    #pragma unroll
                    for (int k = 0; k < 8; k++)
                        v8[k] = fmaf(ew1[(size_t)((cg * 8 + k) * 2 + c) * 9 + dy * 3 + dx], v, v8[k]);
                }
            }
        }
        #pragma unroll
        for (int k = 0; k < 8; k++) v8[k] = fmaxf(v8[k], 0.f);
    } else {
        float dy = pm[(size_t)(img * 2 + 0) * HWP + px];
        float dx = pm[(size_t)(img * 2 + 1) * HWP + px];
        float gy = (float)i + dy, gx = (float)j + dx;
        float fy = floorf(gy), fx = floorf(gx);
        float ty = gy - fy, tx = gx - fx;
        int y0 = (int)fy, x0 = (int)fx;
        int y1 = y0 + 1, x1 = x0 + 1;
        bool vy0 = (unsigned)y0 < (unsigned)HH, vy1 = (unsigned)y1 < (unsigned)HH;
        bool vx0 = (unsigned)x0 < (unsigned)WW, vx1 = (unsigned)x1 < (unsigned)WW;
        float w00 = (vy0 && vx0) ? (1.f - ty) * (1.f - tx) : 0.f;
        float w01 = (vy0 && vx1) ? (1.f - ty) * tx         : 0.f;
        float w10 = (vy1 && vx0) ? ty * (1.f - tx)         : 0.f;
        float w11 = (vy1 && vx1) ? ty * tx                 : 0.f;
        int y0c = min(max(y0, 0), HH - 1), y1c = min(max(y1, 0), HH - 1);
        int x0c = min(max(x0, 0), WW - 1), x1c = min(max(x1, 0), WW - 1);
        int i00 = y0c * WW + x0c, i01 = y0c * WW + x1c;
        int i10 = y1c * WW + x0c, i11 = y1c * WW + x1c;
        const float* f = feat + ((size_t)(img / 3) * CH + cg * 8) * HWP;
        #pragma unroll
        for (int c = 0; c < 8; c++) {
            const float* fc = f + (size_t)c * HWP;
            v8[c] = w00 * fc[i00] + w01 * fc[i01] + w10 * fc[i10] + w11 * fc[i11];
        }
    }
    __nv_bfloat16 h[8], l[8];
    #pragma unroll
    for (int k = 0; k < 8; k++) {
        __nv_bfloat16 hv = __float2bfloat16_rn(v8[k]);
        h[k] = hv;
        l[k] = __float2bfloat16_rn(v8[k] - __bfloat162float(hv));
    }
    size_t dst = ((size_t)img * PHWP + i * PW + j + 1) * CH + cg * 8;
    __nv_bfloat16* oh = blockIdx.y == 0 ? g_E0h : g_P0h;
    __nv_bfloat16* ol = blockIdx.y == 0 ? g_E0l : g_P0l;
    *(uint4*)(oh + dst) = *(uint4*)h;
    *(uint4*)(ol + dst) = *(uint4*)l;
}

// ---------------------------------------------------------------------------
// weight prep: OIHW fp32 -> [tap][oc][ic] bf16 hi/lo
// ---------------------------------------------------------------------------
__global__ void prep_w3_k(const float* __restrict__ w,
                          __nv_bfloat16* __restrict__ wh, __nv_bfloat16* __restrict__ wl) {
    int idx = blockIdx.x * 256 + threadIdx.x;
    if (idx >= 9 * CH * CH) return;
    int tap = idx / (CH * CH);
    int rem = idx - tap * (CH * CH);
    int oc = rem >> 8, ic = rem & 255;
    float v = w[(size_t)(oc * CH + ic) * 9 + tap];
    __nv_bfloat16 hv = __float2bfloat16_rn(v);
    wh[idx] = hv;
    wl[idx] = __float2bfloat16_rn(v - __bfloat162float(hv));
}
__global__ void prep_w1_k(const float* __restrict__ w,
                          __nv_bfloat16* __restrict__ wh, __nv_bfloat16* __restrict__ wl) {
    int idx = blockIdx.x * 256 + threadIdx.x;
    if (idx >= CH * CH) return;
    float v = w[idx];
    __nv_bfloat16 hv = __float2bfloat16_rn(v);
    wh[idx] = hv;
    wl[idx] = __float2bfloat16_rn(v - __bfloat162float(hv));
}

// ---------------------------------------------------------------------------
// staging + compute (identical to R11)
// ---------------------------------------------------------------------------
__device__ __forceinline__ void stage_A(uint32_t sb, uint32_t bufoff,
                                        const __nv_bfloat16* wh, const __nv_bfloat16* wl,
                                        int tap, int ocb, int ic0, int tid) {
    #pragma unroll
    for (int i = 0; i < 8; i++) {
        int idx = tid + i * 256;
        int half = idx >> 10;
        int r = idx & 1023;
        int row = r >> 3, seg = r & 7;
        size_t g = ((size_t)(tap * CH + ocb * 128 + row)) * CH + ic0 + seg * 8;
        uint32_t dst = sb + bufoff + (uint32_t)half * (128 * RS) + (uint32_t)row * RS + seg * 16;
        cpa16(dst, (half ? wl : wh) + g, true);
    }
}
__device__ __forceinline__ void stage_B(uint32_t sb,
                                        const __nv_bfloat16* xh, const __nv_bfloat16* xl,
                                        int pstart, int tid) {
    #pragma unroll
    for (int i = 0; i < 8; i++) {
        int idx = tid + i * 256;
        if (idx >= 1856) break;
        int half = idx >= 928;
        int r = idx - half * 928;
        int row = r >> 3, seg = r & 7;
        int p = pstart + row;
        bool valid = (p >= 0) && (p < HH * PW);
        size_t g = (size_t)(valid ? p : 0) * CH + seg * 8;
        uint32_t dst = sb + SM_B + (uint32_t)half * (116 * RS) + (uint32_t)row * RS + seg * 16;
        cpa16(dst, (half ? xl : xh) + g, valid);
    }
}
__device__ __forceinline__ void do_compute(uint32_t sb, uint32_t abuf, int dx,
                                           int wm, int wn, int lane, float acc[2][7][4]) {
    const uint32_t aRow = wm * 32 + (lane & 15);
    const uint32_t aHi = sb + abuf + aRow * RS + (uint32_t)((lane >> 4) & 1) * 16;
    const uint32_t aLo = aHi + 128 * RS;
    const uint32_t bRow = wn * 58 + 1 + dx + (lane & 7);
    const uint32_t bHi = sb + SM_B + bRow * RS + (uint32_t)((lane >> 3) & 1) * 16;
    const uint32_t bLo = bHi + 116 * RS;
    #pragma unroll
    for (int ks = 0; ks < 4; ks++) {
        uint32_t ah[2][4], al[2][4];
        #pragma unroll
        for (int mf = 0; mf < 2; mf++) {
            ldsm_x4(ah[mf], aHi + mf * 16 * RS + ks * 32);
            ldsm_x4(al[mf], aLo + mf * 16 * RS + ks * 32);
        }
        #pragma unroll
        for (int nf = 0; nf < 7; nf++) {
            uint32_t bh[2], bl[2];
            ldsm_x2(bh, bHi + nf * 8 * RS + ks * 32);
            ldsm_x2(bl, bLo + nf * 8 * RS + ks * 32);
            #pragma unroll
            for (int mf = 0; mf < 2; mf++) {
                float* d = &acc[mf][nf][0];
                mma16816(d, ah[mf], bh);
                mma16816(d, ah[mf], bl);
                mma16816(d, al[mf], bh);
            }
        }
    }
}

// ---------------------------------------------------------------------------
// Templated HMMA implicit-GEMM conv (R11 mainloop). Compile-time epilogue:
//   XT_MODE=0: fp32 out (+bias/relu/residual)
//   XT_MODE=1: bf16 hi/lo xt emit via smem transpose (separate reg alloc!)
// ---------------------------------------------------------------------------
#define ST_STRIDE 132

template <int NTAPS, bool RELU, bool HAS_EXTRA, bool XT_MODE>
__global__ __launch_bounds__(256, 2)
void gemm_conv_k(const __nv_bfloat16* __restrict__ xt_hi, const __nv_bfloat16* __restrict__ xt_lo,
                 const __nv_bfloat16* __restrict__ wA_hi, const __nv_bfloat16* __restrict__ wA_lo,
                 const float* __restrict__ bias, const float* __restrict__ extra,
                 float* __restrict__ out_f32,
                 __nv_bfloat16* __restrict__ out_xh, __nv_bfloat16* __restrict__ out_xl) {
    extern __shared__ char smem[];
    const uint32_t sb = smem_u32(smem);
    const int tid = threadIdx.x;
    const int warp = tid >> 5, lane = tid & 31;
    const int wm = warp & 3, wn = warp >> 2;
    const int pxb = blockIdx.x, ocb = blockIdx.y, img = blockIdx.z;
    const int p0 = pxb * 112;
    const int r0 = p0 / WW;

    const __nv_bfloat16* xh = xt_hi + (size_t)img * PHWP * CH;
    const __nv_bfloat16* xl = xt_lo + (size_t)img * PHWP * CH;

    float acc[2][7][4];
    #pragma unroll
    for (int mf = 0; mf < 2; mf++)
        #pragma unroll
        for (int nf = 0; nf < 7; nf++)
            #pragma unroll
            for (int k = 0; k < 4; k++) acc[mf][nf][k] = 0.f;

    if (NTAPS == 9) {
        for (int ic0 = 0; ic0 < CH; ic0 += 64) {
            #pragma unroll
            for (int dy3 = 0; dy3 < 3; dy3++) {
                const int dy = dy3 - 1;
                __syncthreads();
                stage_B(sb, xh + ic0, xl + ic0, (r0 + dy) * PW, tid);
                stage_A(sb, SM_A0, wA_hi, wA_lo, dy3 * 3 + 0, ocb, ic0, tid);
                CPA_COMMIT();
                stage_A(sb, SM_A1, wA_hi, wA_lo, dy3 * 3 + 1, ocb, ic0, tid);
                CPA_COMMIT();
                cpa_wait<1>();  __syncthreads();
                do_compute(sb, SM_A0, -1, wm, wn, lane, acc);
                __syncthreads();
                stage_A(sb, SM_A0, wA_hi, wA_lo, dy3 * 3 + 2, ocb, ic0, tid);
                CPA_COMMIT();
                cpa_wait<1>();  __syncthreads();
                do_compute(sb, SM_A1, 0, wm, wn, lane, acc);
                cpa_wait<0>();  __syncthreads();
                do_compute(sb, SM_A0, +1, wm, wn, lane, acc);
            }
        }
    } else {
        for (int ic0 = 0; ic0 < CH; ic0 += 64) {
            __syncthreads();
            stage_B(sb, xh + ic0, xl + ic0, r0 * PW, tid);
            stage_A(sb, SM_A0, wA_hi, wA_lo, 0, ocb, ic0, tid);
            CPA_COMMIT();
            cpa_wait<0>();  __syncthreads();
            do_compute(sb, SM_A0, 0, wm, wn, lane, acc);
        }
    }

    const int qr = lane >> 2, qc = 2 * (lane & 3);
    if (!XT_MODE) {
        #pragma unroll
        for (int mf = 0; mf < 2; mf++) {
            #pragma unroll
            for (int half = 0; half < 2; half++) {
                int oc = ocb * 128 + wm * 32 + mf * 16 + qr + half * 8;
                float b = bias[oc];
                size_t obase = ((size_t)img * CH + oc) * HWP + p0 + wn * 56;
                #pragma unroll
                for (int nf = 0; nf < 7; nf++) {
                    size_t o = obase + nf * 8 + qc;
                    float v0 = acc[mf][nf][half * 2 + 0] + b;
                    float v1 = acc[mf][nf][half * 2 + 1] + b;
                    if (RELU) { v0 = fmaxf(v0, 0.f); v1 = fmaxf(v1, 0.f); }
                    if (HAS_EXTRA) {
                        float2 e = *(const float2*)(extra + o);
                        v0 += e.x; v1 += e.y;
                    }
                    float2 r; r.x = v0; r.y = v1;
                    *(float2*)(out_f32 + o) = r;
                }
            }
        }
    } else {
        __syncthreads();                       // mainloop smem reads done
        float* sT = (float*)smem;
        #pragma unroll
        for (int mf = 0; mf < 2; mf++) {
            #pragma unroll
            for (int half = 0; half < 2; half++) {
                int ocl = wm * 32 + mf * 16 + qr + half * 8;
                float b = bias[ocb * 128 + ocl];
                #pragma unroll
                for (int nf = 0; nf < 7; nf++) {
                    int pxl = wn * 56 + nf * 8 + qc;
                    float v0 = acc[mf][nf][half * 2 + 0] + b;
                    float v1 = acc[mf][nf][half * 2 + 1] + b;
                    if (RELU) { v0 = fmaxf(v0, 0.f); v1 = fmaxf(v1, 0.f); }
                    sT[(pxl + 0) * ST_STRIDE + ocl] = v0;
                    sT[(pxl + 1) * ST_STRIDE + ocl] = v1;
                }
            }
        }
        __syncthreads();
        #pragma unroll
        for (int i = 0; i < 7; i++) {
            int idx = tid + i * 256;             // 0..1791
            int px = idx >> 4, g = idx & 15;
            const float* srow = sT + px * ST_STRIDE + g * 8;
            __nv_bfloat16 h[8], l[8];
            #pragma unroll
            for (int k = 0; k < 8; k++) {
                float v = srow[k];
                __nv_bfloat16 hv = __float2bfloat16_rn(v);
                h[k] = hv;
                l[k] = __float2bfloat16_rn(v - __bfloat162float(hv));
            }
            size_t dst = ((size_t)img * PHWP + (size_t)(r0 + (px / 56)) * PW + (px % 56) + 1) * CH
                         + ocb * 128 + g * 8;
            *(uint4*)(out_xh + dst) = *(uint4*)h;
            *(uint4*)(out_xl + dst) = *(uint4*)l;
        }
    }
}

// ---------------------------------------------------------------------------
__global__ void pool_k(const float* __restrict__ p2d, float* __restrict__ pooled) {
    int nc = blockIdx.x;
    const float* src = p2d + (size_t)nc * HWP;
    float s = 0.f;
    for (int i = threadIdx.x; i < HWP; i += 256) s += src[i];
    #pragma unroll
    for (int o = 16; o > 0; o >>= 1) s += __shfl_xor_sync(0xffffffffu, s, o);
    __shared__ float sm[8];
    if ((threadIdx.x & 31) == 0) sm[threadIdx.x >> 5] = s;
    __syncthreads();
    if (threadIdx.x < 8) {
        s = sm[threadIdx.x];
        #pragma unroll
        for (int o = 4; o > 0; o >>= 1) s += __shfl_xor_sync(0xffu, s, o);
        if (threadIdx.x == 0) pooled[nc] = s * (1.f / (float)HWP);
    }
}

// ---------------------------------------------------------------------------
extern "C" void kernel_launch(void* const* d_in, const int* in_sizes, int n_in,
                              void* d_out, int out_size) {
    const float* i_features = (const float*)d_in[1];
    const float* p_motions  = (const float*)d_in[2];
    const float* dw  = (const float*)d_in[3];
    const float* db  = (const float*)d_in[4];
    const float* mw1 = (const float*)d_in[5];
    const float* mb1 = (const float*)d_in[6];
    const float* mw2 = (const float*)d_in[7];
    const float* mb2 = (const float*)d_in[8];
    const float* mw3 = (const float*)d_in[9];
    const float* mb3 = (const float*)d_in[10];
    const float* ew1 = (const float*)d_in[11];
    const float* eb1 = (const float*)d_in[12];
    const float* ew2 = (const float*)d_in[13];
    const float* eb2 = (const float*)d_in[14];
    const float* ew3 = (const float*)d_in[15];
    const float* eb3 = (const float*)d_in[16];
    const float* ew4 = (const float*)d_in[17];
    const float* eb4 = (const float*)d_in[18];
    float* out = (float*)d_out;

    float *pm, *bC;
    cudaGetSymbolAddress((void**)&pm, g_pm);
    cudaGetSymbolAddress((void**)&bC, g_bufC);
    __nv_bfloat16 *E0h,*E0l,*E1h,*E1l,*P0h,*P0l,*P1h,*P1l,*wh,*wl,*wdh,*wdl;
    cudaGetSymbolAddress((void**)&E0h, g_E0h); cudaGetSymbolAddress((void**)&E0l, g_E0l);
    cudaGetSymbolAddress((void**)&E1h, g_E1h); cudaGetSymbolAddress((void**)&E1l, g_E1l);
    cudaGetSymbolAddress((void**)&P0h, g_P0h); cudaGetSymbolAddress((void**)&P0l, g_P0l);
    cudaGetSymbolAddress((void**)&P1h, g_P1h); cudaGetSymbolAddress((void**)&P1l, g_P1l);
    cudaGetSymbolAddress((void**)&wh,  g_wA_hi); cudaGetSymbolAddress((void**)&wl,  g_wA_lo);
    cudaGetSymbolAddress((void**)&wdh, g_wd_hi); cudaGetSymbolAddress((void**)&wdl, g_wd_lo);

    cudaFuncSetAttribute(gemm_conv_k<9, true,  false, true >, cudaFuncAttributeMaxDynamicSharedMemorySize, SM_TOT);
    cudaFuncSetAttribute(gemm_conv_k<9, true,  false, false>, cudaFuncAttributeMaxDynamicSharedMemorySize, SM_TOT);
    cudaFuncSetAttribute(gemm_conv_k<9, true,  true,  false>, cudaFuncAttributeMaxDynamicSharedMemorySize, SM_TOT);
    cudaFuncSetAttribute(gemm_conv_k<1, false, false, true >, cudaFuncAttributeMaxDynamicSharedMemorySize, SM_TOT);

    float* pooled = out;
    float* p2d    = out + 6144;

    const dim3 gg(28, 2, N_IMG);
    const int W3 = cdiv(9 * CH * CH, 256);
    const int W1 = cdiv(CH * CH, 256);
    const int PB = cdiv(N_IMG * HWP * 32, 256);

    downsample_k<<<cdiv(48 * HWP, 256), 256>>>(p_motions, pm);               // 0
    init_pads_k<<<cdiv(N_IMG * HH * 2 * 32, 256), 256>>>();                  // 1
    prep_in_k<<<dim3(PB, 2, 1), 256>>>(pm, i_features, ew1, eb1);            // 2 -> E0, P0
    prep_w3_k<<<W3, 256>>>(ew2, wh, wl);                                     // 3
    prep_w1_k<<<W1, 256>>>(dw, wdh, wdl);                                    // 4

    // e2: E0 -> E1 (xt)                                                     // 5 (ncu slot)
    gemm_conv_k<9, true, false, true><<<gg, 256, SM_TOT>>>(
        E0h, E0l, wh, wl, eb2, nullptr, nullptr, E1h, E1l);
    // 1x1: P0 -> P1 (xt, no relu)
    gemm_conv_k<1, false, false, true><<<gg, 256, SM_TOT>>>(
        P0h, P0l, wdh, wdl, db, nullptr, nullptr, P1h, P1l);

    prep_w3_k<<<W3, 256>>>(ew3, wh, wl);
    // e3: E1 -> E0 (xt)
    gemm_conv_k<9, true, false, true><<<gg, 256, SM_TOT>>>(
        E1h, E1l, wh, wl, eb3, nullptr, nullptr, E0h, E0l);

    prep_w3_k<<<W3, 256>>>(mw1, wh, wl);
    // m1: P1 -> P0 (xt)
    gemm_conv_k<9, true, false, true><<<gg, 256, SM_TOT>>>(
        P1h, P1l, wh, wl, mb1, nullptr, nullptr, P0h, P0l);

    prep_w3_k<<<W3, 256>>>(ew4, wh, wl);
    // e4: E0 -> bufC (fp32)
    gemm_conv_k<9, true, false, false><<<gg, 256, SM_TOT>>>(
        E0h, E0l, wh, wl, eb4, nullptr, bC, nullptr, nullptr);

    prep_w3_k<<<W3, 256>>>(mw2, wh, wl);
    // m2: P0 -> P1 (xt)
    gemm_conv_k<9, true, false, true><<<gg, 256, SM_TOT>>>(
        P0h, P0l, wh, wl, mb2, nullptr, nullptr, P1h, P1l);

    prep_w3_k<<<W3, 256>>>(mw3, wh, wl);
    // m3: P1 -> p2d (fp32, + emb residual)
    gemm_conv_k<9, true, true, false><<<gg, 256, SM_TOT>>>(
        P1h, P1l, wh, wl, mb3, bC, p2d, nullptr, nullptr);

    pool_k<<<N_IMG * CH, 256>>>(p2d, pooled);
}

// round 17
// speedup vs baseline: 1.1152x; 1.1152x over previous
#include <cuda_runtime.h>
#include <cuda_bf16.h>
#include <cstdint>

// ---------------------------------------------------------------------------
// UpsampleUpdatingModel2 — split-bf16 implicit-GEMM convs on mma.sync (HMMA)
// R16: R11 chassis (best 3920us) + prep-tail fusion:
//   - all weight preps in one upfront launch (6x w3 + 1x w1 buffers)
//   - alternating emb/pf chains; each GEMM launch carries the other chain's
//     prep_xt blocks as extra z-CTAs (R9-proven mechanism, fp32 epilogue kept)
// ---------------------------------------------------------------------------

#define N_IMG 24
#define CH    256
#define HH    56
#define WW    56
#define HWP   3136
#define PW    58
#define PHWP  3248
#define XT_ELEMS ((size_t)N_IMG * PHWP * CH)
#define W3SZ  (9 * CH * CH)

__device__ __align__(128) float g_pm [N_IMG * 2 * HWP];
__device__ __align__(128) float g_eA [N_IMG * CH * HWP];
__device__ __align__(128) float g_eB [N_IMG * CH * HWP];
__device__ __align__(128) float g_pA [N_IMG * CH * HWP];
__device__ __align__(128) float g_pB [N_IMG * CH * HWP];
__device__ __align__(128) float g_bufC[N_IMG * CH * HWP];
__device__ __align__(128) __nv_bfloat16 g_xEh[XT_ELEMS], g_xEl[XT_ELEMS];
__device__ __align__(128) __nv_bfloat16 g_xPh[XT_ELEMS], g_xPl[XT_ELEMS];
__device__ __align__(128) __nv_bfloat16 g_w3h[6 * W3SZ], g_w3l[6 * W3SZ]; // e2,e3,e4,m1,m2,m3
__device__ __align__(128) __nv_bfloat16 g_wdh[CH * CH],  g_wdl[CH * CH];

static inline int cdiv(int a, int b) { return (a + b - 1) / b; }

// ------------------------------ PTX helpers --------------------------------
__device__ __forceinline__ uint32_t smem_u32(const void* p) {
    uint32_t a;
    asm("{ .reg .u64 t; cvta.to.shared.u64 t, %1; cvt.u32.u64 %0, t; }" : "=r"(a) : "l"(p));
    return a;
}
__device__ __forceinline__ void ldsm_x4(uint32_t* r, uint32_t addr) {
    asm volatile("ldmatrix.sync.aligned.m8n8.x4.shared.b16 {%0,%1,%2,%3}, [%4];"
                 : "=r"(r[0]), "=r"(r[1]), "=r"(r[2]), "=r"(r[3]) : "r"(addr));
}
__device__ __forceinline__ void ldsm_x2(uint32_t* r, uint32_t addr) {
    asm volatile("ldmatrix.sync.aligned.m8n8.x2.shared.b16 {%0,%1}, [%2];"
                 : "=r"(r[0]), "=r"(r[1]) : "r"(addr));
}
__device__ __forceinline__ void mma16816(float* d, const uint32_t* a, const uint32_t* b) {
    asm volatile(
        "mma.sync.aligned.m16n8k16.row.col.f32.bf16.bf16.f32 "
        "{%0,%1,%2,%3}, {%4,%5,%6,%7}, {%8,%9}, {%0,%1,%2,%3};"
        : "+f"(d[0]), "+f"(d[1]), "+f"(d[2]), "+f"(d[3])
        : "r"(a[0]), "r"(a[1]), "r"(a[2]), "r"(a[3]), "r"(b[0]), "r"(b[1]));
}
__device__ __forceinline__ void cpa16(uint32_t dst, const void* src, bool valid) {
    asm volatile("cp.async.cg.shared.global [%0], [%1], 16, %2;"
                 :: "r"(dst), "l"(src), "r"(valid ? 16u : 0u));
}
#define CPA_COMMIT() asm volatile("cp.async.commit_group;")
template <int N>
__device__ __forceinline__ void cpa_wait() {
    asm volatile("cp.async.wait_group %0;" :: "n"(N));
}

// SMEM layout (identical to R11): occ 2
#define RS     144
#define A_BUF  (2 * 128 * RS)
#define SM_A0  0
#define SM_A1  (SM_A0 + A_BUF)
#define SM_B   (SM_A1 + A_BUF)
#define SM_TOT (SM_B + 2 * 116 * RS)        // 107136

// ---------------------------------------------------------------------------
__global__ void downsample_k(const float* __restrict__ src, float* __restrict__ dst) {
    int idx = blockIdx.x * 256 + threadIdx.x;
    if (idx >= 48 * HWP) return;
    int nc = idx / HWP, p = idx - nc * HWP;
    int i = p / WW, j = p - i * WW;
    const float* s = src + (size_t)nc * 112 * 112;
    int base = (2 * i) * 112 + 2 * j;
    dst[idx] = (s[base] + s[base + 1] + s[base + 112] + s[base + 113]) * 0.0625f;
}

// ---------------------------------------------------------------------------
// all weight preps (6x conv3x3 OIHW + 1x 1x1) in one launch
// ---------------------------------------------------------------------------
__global__ void prep_w_all_k(const float* __restrict__ e2, const float* __restrict__ e3,
                             const float* __restrict__ e4, const float* __restrict__ m1,
                             const float* __restrict__ m2, const float* __restrict__ m3,
                             const float* __restrict__ dwp) {
    int idx = blockIdx.x * 256 + threadIdx.x;
    if (idx < 6 * W3SZ) {
        int j = idx / W3SZ, rem = idx - j * W3SZ;
        int tap = rem / (CH * CH);
        int r2 = rem - tap * (CH * CH);
        int oc = r2 >> 8, ic = r2 & 255;
        const float* s = (j == 0) ? e2 : (j == 1) ? e3 : (j == 2) ? e4
                       : (j == 3) ? m1 : (j == 4) ? m2 : m3;
        float v = s[(size_t)(oc * CH + ic) * 9 + tap];
        __nv_bfloat16 hv = __float2bfloat16_rn(v);
        g_w3h[idx] = hv;
        g_w3l[idx] = __float2bfloat16_rn(v - __bfloat162float(hv));
    } else {
        int r = idx - 6 * W3SZ;
        if (r >= CH * CH) return;
        float v = dwp[r];
        __nv_bfloat16 hv = __float2bfloat16_rn(v);
        g_wdh[r] = hv;
        g_wdl[r] = __float2bfloat16_rn(v - __bfloat162float(hv));
    }
}

// ---------------------------------------------------------------------------
__global__ void conv_first_k(const float* __restrict__ pm, const float* __restrict__ wt,
                             const float* __restrict__ bias, float* __restrict__ out) {
    int idx = blockIdx.x * 256 + threadIdx.x;
    if (idx >= N_IMG * CH * HWP) return;
    int p = idx % HWP;
    int o = (idx / HWP) & (CH - 1);
    int n = idx / (CH * HWP);
    int i = p / WW, j = p - (p / WW) * WW;
    float s = bias[o];
    #pragma unroll
    for (int c = 0; c < 2; c++) {
        const float* pc = pm + (size_t)(n * 2 + c) * HWP;
        const float* wc = wt + (size_t)(o * 2 + c) * 9;
        #pragma unroll
        for (int dy = 0; dy < 3; dy++) {
            int y = i + dy - 1;
            if ((unsigned)y >= (unsigned)HH) continue;
            #pragma unroll
            for (int dx = 0; dx < 3; dx++) {
                int x = j + dx - 1;
                if ((unsigned)x >= (unsigned)WW) continue;
                s = fmaf(wc[dy * 3 + dx], pc[y * WW + x], s);
            }
        }
    }
    out[idx] = fmaxf(s, 0.f);
}

// ---------------------------------------------------------------------------
__global__ void deform_k(const float* __restrict__ feat, const float* __restrict__ pm,
                         float* __restrict__ out) {
    int idx = blockIdx.x * 256 + threadIdx.x;
    if (idx >= N_IMG * 32 * HWP) return;
    int p  = idx % HWP;
    int cg = (idx / HWP) & 31;
    int n  = idx / (32 * HWP);
    int i = p / WW, j = p - (p / WW) * WW;

    float dy = pm[(size_t)(n * 2 + 0) * HWP + p];
    float dx = pm[(size_t)(n * 2 + 1) * HWP + p];
    float gy = (float)i + dy, gx = (float)j + dx;
    float fy = floorf(gy), fx = floorf(gx);
    float ty = gy - fy, tx = gx - fx;
    int y0 = (int)fy, x0 = (int)fx;
    int y1 = y0 + 1, x1 = x0 + 1;
    bool vy0 = (unsigned)y0 < (unsigned)HH, vy1 = (unsigned)y1 < (unsigned)HH;
    bool vx0 = (unsigned)x0 < (unsigned)WW, vx1 = (unsigned)x1 < (unsigned)WW;
    float w00 = (vy0 && vx0) ? (1.f - ty) * (1.f - tx) : 0.f;
    float w01 = (vy0 && vx1) ? (1.f - ty) * tx         : 0.f;
    float w10 = (vy1 && vx0) ? ty * (1.f - tx)         : 0.f;
    float w11 = (vy1 && vx1) ? ty * tx                 : 0.f;
    int y0c = min(max(y0, 0), HH - 1), y1c = min(max(y1, 0), HH - 1);
    int x0c = min(max(x0, 0), WW - 1), x1c = min(max(x1, 0), WW - 1);
    int i00 = y0c * WW + x0c, i01 = y0c * WW + x1c;
    int i10 = y1c * WW + x0c, i11 = y1c * WW + x1c;

    const float* f = feat + ((size_t)(n / 3) * CH + cg * 8) * HWP;
    float* o = out + ((size_t)n * CH + cg * 8) * HWP + p;
    #pragma unroll
    for (int c = 0; c < 8; c++) {
        const float* fc = f + (size_t)c * HWP;
        o[(size_t)c * HWP] = w00 * fc[i00] + w01 * fc[i01] + w10 * fc[i10] + w11 * fc[i11];
    }
}

// ---------------------------------------------------------------------------
// prep_xt block body (R11's smem-transpose, refactored for reuse).
// One call handles a (112 px, 64 ch) tile of one image.
// ---------------------------------------------------------------------------
__device__ __forceinline__ void prep_xt_block(const float* __restrict__ in,
                                              __nv_bfloat16* __restrict__ xh,
                                              __nv_bfloat16* __restrict__ xl,
                                              int img, int pxb, int cb, int tid,
                                              float* sT /* 64*113 floats */) {
    const int p0 = pxb * 112;
    #pragma unroll
    for (int i = 0; i < 7; i++) {
        int idx = tid + i * 256;                 // 0..1791
        int ch = idx / 28, sg = idx - (idx / 28) * 28;
        const float* src = in + ((size_t)(img * CH + cb * 64 + ch)) * HWP + p0 + sg * 4;
        float4 v = *(const float4*)src;
        sT[ch * 113 + sg * 4 + 0] = v.x;  sT[ch * 113 + sg * 4 + 1] = v.y;
        sT[ch * 113 + sg * 4 + 2] = v.z;  sT[ch * 113 + sg * 4 + 3] = v.w;
    }
    __syncthreads();
    #pragma unroll
    for (int i = 0; i < 4; i++) {
        int idx = tid + i * 256;
        if (idx >= 896) break;
        int pxl = idx >> 3, g = idx & 7;
        int px = p0 + pxl;
        int r = px / WW, c = px - r * WW;
        __nv_bfloat16 h[8], l[8];
        #pragma unroll
        for (int k = 0; k < 8; k++) {
            float v = sT[(g * 8 + k) * 113 + pxl];
            __nv_bfloat16 hv = __float2bfloat16_rn(v);
            h[k] = hv;
            l[k] = __float2bfloat16_rn(v - __bfloat162float(hv));
        }
        size_t dst = ((size_t)img * PHWP + r * PW + c + 1) * CH + cb * 64 + g * 8;
        *(uint4*)(xh + dst) = *(uint4*)h;
        *(uint4*)(xl + dst) = *(uint4*)l;
        uint4 z = {0, 0, 0, 0};
        if (c == 0) {
            size_t d0 = ((size_t)img * PHWP + r * PW + 0) * CH + cb * 64 + g * 8;
            *(uint4*)(xh + d0) = z;  *(uint4*)(xl + d0) = z;
        }
        if (c == WW - 1) {
            size_t d1 = ((size_t)img * PHWP + r * PW + 57) * CH + cb * 64 + g * 8;
            *(uint4*)(xh + d1) = z;  *(uint4*)(xl + d1) = z;
        }
    }
}

// standalone dual-chain prep_xt: grid (28, 4, 24 or 48)
__global__ __launch_bounds__(256)
void prep_xt2_k(const float* __restrict__ sE, __nv_bfloat16* __restrict__ xEh,
                __nv_bfloat16* __restrict__ xEl,
                const float* __restrict__ sP, __nv_bfloat16* __restrict__ xPh,
                __nv_bfloat16* __restrict__ xPl) {
    __shared__ float sT[64 * 113];
    int z = blockIdx.z;
    const float* s; __nv_bfloat16 *xh, *xl; int img;
    if (z < N_IMG) { s = sE; xh = xEh; xl = xEl; img = z; }
    else           { s = sP; xh = xPh; xl = xPl; img = z - N_IMG; }
    prep_xt_block(s, xh, xl, img, blockIdx.x, blockIdx.y, threadIdx.x, sT);
}

// ---------------------------------------------------------------------------
// staging + compute (identical to R11)
// ---------------------------------------------------------------------------
__device__ __forceinline__ void stage_A(uint32_t sb, uint32_t bufoff,
                                        const __nv_bfloat16* wh, const __nv_bfloat16* wl,
                                        int tap, int ocb, int ic0, int tid) {
    #pragma unroll
    for (int i = 0; i < 8; i++) {
        int idx = tid + i * 256;
        int half = idx >> 10;
        int r = idx & 1023;
        int row = r >> 3, seg = r & 7;
        size_t g = ((size_t)(tap * CH + ocb * 128 + row)) * CH + ic0 + seg * 8;
        uint32_t dst = sb + bufoff + (uint32_t)half * (128 * RS) + (uint32_t)row * RS + seg * 16;
        cpa16(dst, (half ? wl : wh) + g, true);
    }
}
__device__ __forceinline__ void stage_B(uint32_t sb,
                                        const __nv_bfloat16* xh, const __nv_bfloat16* xl,
                                        int pstart, int tid) {
    #pragma unroll
    for (int i = 0; i < 8; i++) {
        int idx = tid + i * 256;
        if (idx >= 1856) break;
        int half = idx >= 928;
        int r = idx - half * 928;
        int row = r >> 3, seg = r & 7;
        int p = pstart + row;
        bool valid = (p >= 0) && (p < HH * PW);
        size_t g = (size_t)(valid ? p : 0) * CH + seg * 8;
        uint32_t dst = sb + SM_B + (uint32_t)half * (116 * RS) + (uint32_t)row * RS + seg * 16;
        cpa16(dst, (half ? xl : xh) + g, valid);
    }
}
__device__ __forceinline__ void do_compute(uint32_t sb, uint32_t abuf, int dx,
                                           int wm, int wn, int lane, float acc[2][7][4]) {
    const uint32_t aRow = wm * 32 + (lane & 15);
    const uint32_t aHi = sb + abuf + aRow * RS + (uint32_t)((lane >> 4) & 1) * 16;
    const uint32_t aLo = aHi + 128 * RS;
    const uint32_t bRow = wn * 58 + 1 + dx + (lane & 7);
    const uint32_t bHi = sb + SM_B + bRow * RS + (uint32_t)((lane >> 3) & 1) * 16;
    const uint32_t bLo = bHi + 116 * RS;
    #pragma unroll
    for (int ks = 0; ks < 4; ks++) {
        uint32_t ah[2][4], al[2][4];
        #pragma unroll
        for (int mf = 0; mf < 2; mf++) {
            ldsm_x4(ah[mf], aHi + mf * 16 * RS + ks * 32);
            ldsm_x4(al[mf], aLo + mf * 16 * RS + ks * 32);
        }
        #pragma unroll
        for (int nf = 0; nf < 7; nf++) {
            uint32_t bh[2], bl[2];
            ldsm_x2(bh, bHi + nf * 8 * RS + ks * 32);
            ldsm_x2(bl, bLo + nf * 8 * RS + ks * 32);
            #pragma unroll
            for (int mf = 0; mf < 2; mf++) {
                float* d = &acc[mf][nf][0];
                mma16816(d, ah[mf], bh);
                mma16816(d, ah[mf], bl);
                mma16816(d, al[mf], bh);
            }
        }
    }
}

// ---------------------------------------------------------------------------
// HMMA implicit-GEMM conv (R11 mainloop + fp32 epilogue), with optional
// prep-tail: blocks with z >= N_IMG run the other chain's prep_xt instead.
// ---------------------------------------------------------------------------
__global__ __launch_bounds__(256, 2)
void gemm_conv_k(const __nv_bfloat16* __restrict__ xt_hi, const __nv_bfloat16* __restrict__ xt_lo,
                 const __nv_bfloat16* __restrict__ wA_hi, const __nv_bfloat16* __restrict__ wA_lo,
                 const float* __restrict__ bias, const float* __restrict__ extra,
                 float* __restrict__ out, int ntaps, int relu, int has_extra,
                 const float* __restrict__ psrc,
                 __nv_bfloat16* __restrict__ pxh, __nv_bfloat16* __restrict__ pxl) {
    extern __shared__ char smem[];

    if (blockIdx.z >= N_IMG) {
        // ---- prep tail: transpose 128 ch (2 chunks) of one px-tile ----
        float* sT = (float*)smem;
        const int img = blockIdx.z - N_IMG;
        #pragma unroll
        for (int pass = 0; pass < 2; pass++) {
            if (pass) __syncthreads();
            prep_xt_block(psrc, pxh, pxl, img, blockIdx.x,
                          blockIdx.y * 2 + pass, threadIdx.x, sT);
        }
        return;
    }

    const uint32_t sb = smem_u32(smem);
    const int tid = threadIdx.x;
    const int warp = tid >> 5, lane = tid & 31;
    const int wm = warp & 3, wn = warp >> 2;
    const int pxb = blockIdx.x, ocb = blockIdx.y, img = blockIdx.z;
    const int p0 = pxb * 112;
    const int r0 = p0 / WW;

    const __nv_bfloat16* xh = xt_hi + (size_t)img * PHWP * CH;
    const __nv_bfloat16* xl = xt_lo + (size_t)img * PHWP * CH;

    float acc[2][7][4];
    #pragma unroll
    for (int mf = 0; mf < 2; mf++)
        #pragma unroll
        for (int nf = 0; nf < 7; nf++)
            #pragma unroll
            for (int k = 0; k < 4; k++) acc[mf][nf][k] = 0.f;

    if (ntaps == 9) {
        for (int ic0 = 0; ic0 < CH; ic0 += 64) {
            #pragma unroll
            for (int dy3 = 0; dy3 < 3; dy3++) {
                const int dy = dy3 - 1;
                __syncthreads();
                stage_B(sb, xh + ic0, xl + ic0, (r0 + dy) * PW, tid);
                stage_A(sb, SM_A0, wA_hi, wA_lo, dy3 * 3 + 0, ocb, ic0, tid);
                CPA_COMMIT();
                stage_A(sb, SM_A1, wA_hi, wA_lo, dy3 * 3 + 1, ocb, ic0, tid);
                CPA_COMMIT();
                cpa_wait<1>();  __syncthreads();
                do_compute(sb, SM_A0, -1, wm, wn, lane, acc);
                __syncthreads();
                stage_A(sb, SM_A0, wA_hi, wA_lo, dy3 * 3 + 2, ocb, ic0, tid);
                CPA_COMMIT();
                cpa_wait<1>();  __syncthreads();
                do_compute(sb, SM_A1, 0, wm, wn, lane, acc);
                cpa_wait<0>();  __syncthreads();
                do_compute(sb, SM_A0, +1, wm, wn, lane, acc);
            }
        }
    } else {
        for (int ic0 = 0; ic0 < CH; ic0 += 64) {
            __syncthreads();
            stage_B(sb, xh + ic0, xl + ic0, r0 * PW, tid);
            stage_A(sb, SM_A0, wA_hi, wA_lo, 0, ocb, ic0, tid);
            CPA_COMMIT();
            cpa_wait<0>();  __syncthreads();
            do_compute(sb, SM_A0, 0, wm, wn, lane, acc);
        }
    }

    const int qr = lane >> 2, qc = 2 * (lane & 3);
    #pragma unroll
    for (int mf = 0; mf < 2; mf++) {
        #pragma unroll
        for (int half = 0; half < 2; half++) {
            int oc = ocb * 128 + wm * 32 + mf * 16 + qr + half * 8;
            float b = bias[oc];
            size_t obase = ((size_t)img * CH + oc) * HWP + p0 + wn * 56;
            #pragma unroll
            for (int nf = 0; nf < 7; nf++) {
                size_t o = obase + nf * 8 + qc;
                float v0 = acc[mf][nf][half * 2 + 0] + b;
                float v1 = acc[mf][nf][half * 2 + 1] + b;
                if (relu) { v0 = fmaxf(v0, 0.f); v1 = fmaxf(v1, 0.f); }
                if (has_extra) {
                    float2 e = *(const float2*)(extra + o);
                    v0 += e.x; v1 += e.y;
                }
                float2 r; r.x = v0; r.y = v1;
                *(float2*)(out + o) = r;
            }
        }
    }
}

// ---------------------------------------------------------------------------
__global__ void pool_k(const float* __restrict__ p2d, float* __restrict__ pooled) {
    int nc = blockIdx.x;
    const float* src = p2d + (size_t)nc * HWP;
    float s = 0.f;
    for (int i = threadIdx.x; i < HWP; i += 256) s += src[i];
    #pragma unroll
    for (int o = 16; o > 0; o >>= 1) s += __shfl_xor_sync(0xffffffffu, s, o);
    __shared__ float sm[8];
    if ((threadIdx.x & 31) == 0) sm[threadIdx.x >> 5] = s;
    __syncthreads();
    if (threadIdx.x < 8) {
        s = sm[threadIdx.x];
        #pragma unroll
        for (int o = 4; o > 0; o >>= 1) s += __shfl_xor_sync(0xffu, s, o);
        if (threadIdx.x == 0) pooled[nc] = s * (1.f / (float)HWP);
    }
}

// ---------------------------------------------------------------------------
extern "C" void kernel_launch(void* const* d_in, const int* in_sizes, int n_in,
                              void* d_out, int out_size) {
    const float* i_features = (const float*)d_in[1];
    const float* p_motions  = (const float*)d_in[2];
    const float* dw  = (const float*)d_in[3];
    const float* db  = (const float*)d_in[4];
    const float* mw1 = (const float*)d_in[5];
    const float* mb1 = (const float*)d_in[6];
    const float* mw2 = (const float*)d_in[7];
    const float* mb2 = (const float*)d_in[8];
    const float* mw3 = (const float*)d_in[9];
    const float* mb3 = (const float*)d_in[10];
    const float* ew1 = (const float*)d_in[11];
    const float* eb1 = (const float*)d_in[12];
    const float* ew2 = (const float*)d_in[13];
    const float* eb2 = (const float*)d_in[14];
    const float* ew3 = (const float*)d_in[15];
    const float* eb3 = (const float*)d_in[16];
    const float* ew4 = (const float*)d_in[17];
    const float* eb4 = (const float*)d_in[18];
    float* out = (float*)d_out;

    float *pm, *eA, *eB, *pA, *pB, *bC;
    cudaGetSymbolAddress((void**)&pm, g_pm);
    cudaGetSymbolAddress((void**)&eA, g_eA);
    cudaGetSymbolAddress((void**)&eB, g_eB);
    cudaGetSymbolAddress((void**)&pA, g_pA);
    cudaGetSymbolAddress((void**)&pB, g_pB);
    cudaGetSymbolAddress((void**)&bC, g_bufC);
    __nv_bfloat16 *xEh, *xEl, *xPh, *xPl, *w3h, *w3l, *wdh, *wdl;
    cudaGetSymbolAddress((void**)&xEh, g_xEh); cudaGetSymbolAddress((void**)&xEl, g_xEl);
    cudaGetSymbolAddress((void**)&xPh, g_xPh); cudaGetSymbolAddress((void**)&xPl, g_xPl);
    cudaGetSymbolAddress((void**)&w3h, g_w3h); cudaGetSymbolAddress((void**)&w3l, g_w3l);
    cudaGetSymbolAddress((void**)&wdh, g_wdh); cudaGetSymbolAddress((void**)&wdl, g_wdl);

    cudaFuncSetAttribute(gemm_conv_k, cudaFuncAttributeMaxDynamicSharedMemorySize, SM_TOT);

    float* pooled = out;
    float* p2d    = out + 6144;

    const dim3 gg (28, 2, N_IMG);          // gemm only
    const dim3 ggp(28, 2, 2 * N_IMG);      // gemm + prep tail
    const int WPB = cdiv(6 * W3SZ + CH * CH, 256);

    // weights buffer slices
    __nv_bfloat16 *wE2h = w3h + 0 * W3SZ, *wE2l = w3l + 0 * W3SZ;
    __nv_bfloat16 *wE3h = w3h + 1 * W3SZ, *wE3l = w3l + 1 * W3SZ;
    __nv_bfloat16 *wE4h = w3h + 2 * W3SZ, *wE4l = w3l + 2 * W3SZ;
    __nv_bfloat16 *wM1h = w3h + 3 * W3SZ, *wM1l = w3l + 3 * W3SZ;
    __nv_bfloat16 *wM2h = w3h + 4 * W3SZ, *wM2l = w3l + 4 * W3SZ;
    __nv_bfloat16 *wM3h = w3h + 5 * W3SZ, *wM3l = w3l + 5 * W3SZ;

    downsample_k<<<cdiv(48 * HWP, 256), 256>>>(p_motions, pm);                 // 0
    prep_w_all_k<<<WPB, 256>>>(ew2, ew3, ew4, mw1, mw2, mw3, dw);              // 1
    conv_first_k<<<cdiv(N_IMG * CH * HWP, 256), 256>>>(pm, ew1, eb1, eA);      // 2
    deform_k<<<cdiv(N_IMG * 32 * HWP, 256), 256>>>(i_features, pm, pA);        // 3
    prep_xt2_k<<<dim3(28, 4, 48), 256>>>(eA, xEh, xEl, pA, xPh, xPl);          // 4

    // 5: e2 (E: xE -> eB), no tail                                [ncu slot]
    gemm_conv_k<<<gg, 256, SM_TOT>>>(xEh, xEl, wE2h, wE2l, eb2, nullptr, eB,
                                     9, 1, 0, nullptr, nullptr, nullptr);
    // 6: 1x1 (P: xP -> pB) + tail: xE <- eB
    gemm_conv_k<<<ggp, 256, SM_TOT>>>(xPh, xPl, wdh, wdl, db, nullptr, pB,
                                      1, 0, 0, eB, xEh, xEl);
    // 7: e3 (E: xE -> eA) + tail: xP <- pB
    gemm_conv_k<<<ggp, 256, SM_TOT>>>(xEh, xEl, wE3h, wE3l, eb3, nullptr, eA,
                                      9, 1, 0, pB, xPh, xPl);
    // 8: m1 (P: xP -> pA) + tail: xE <- eA
    gemm_conv_k<<<ggp, 256, SM_TOT>>>(xPh, xPl, wM1h, wM1l, mb1, nullptr, pA,
                                      9, 1, 0, eA, xEh, xEl);
    // 9: e4 (E: xE -> bufC) + tail: xP <- pA
    gemm_conv_k<<<ggp, 256, SM_TOT>>>(xEh, xEl, wE4h, wE4l, eb4, nullptr, bC,
                                      9, 1, 0, pA, xPh, xPl);
    // 10: m2 (P: xP -> pB), no tail
    gemm_conv_k<<<gg, 256, SM_TOT>>>(xPh, xPl, wM2h, wM2l, mb2, nullptr, pB,
                                     9, 1, 0, nullptr, nullptr, nullptr);
    // 11: xP <- pB (standalone)
    prep_xt2_k<<<dim3(28, 4, 24), 256>>>(pB, xPh, xPl, pB, xPh, xPl);
    // 12: m3 (P: xP -> p2d, + emb residual)
    gemm_conv_k<<<gg, 256, SM_TOT>>>(xPh, xPl, wM3h, wM3l, mb3, bC, p2d,
                                     9, 1, 1, nullptr, nullptr, nullptr);

    pool_k<<<N_IMG * CH, 256>>>(p2d, pooled);
}